// round 9
// baseline (speedup 1.0000x reference)
#include <cuda_runtime.h>
#include <cstdint>

// Problem constants (fixed for this instance):
//   logits:  [B=256, VOCAB=128000] float32
//   save_id: [B=256, HIST=512] int32 (JAX x64 disabled)
//   penalty_value: [1] float32
//   penalty_range: 64
#define B_DIM      256
#define VOCAB_DIM  128000
#define HIST_DIM   512
#define PEN_RANGE  64

#define SEGS_PER_ROW 25
#define SEG_FLOATS   5120
#define SEG_BYTES    (SEG_FLOATS * 4)   // 20480, multiple of 16
#define THREADS      128

// TMA bulk copy pipeline:
//   gmem --cp.async.bulk--> smem --penalty fixup in smem--> cp.async.bulk --> gmem
// Massive bytes-in-flight per SM (~11 resident CTAs x 20KB) vs the LDG path's
// ~55-outstanding-loads/warp cap; targets the observed DRAM under-utilization.
__global__ void __launch_bounds__(THREADS)
apply_penalty_tma(const float* __restrict__ logits,
                  const int*   __restrict__ save_id,
                  const float* __restrict__ penalty,
                  float*       __restrict__ out) {
    __shared__ alignas(128) float buf[SEG_FLOATS];
    __shared__ alignas(8)  unsigned long long mbar;

    const int b   = blockIdx.x;
    const int row = b / SEGS_PER_ROW;
    const int seg = b - row * SEGS_PER_ROW;
    const size_t byte_off = ((size_t)row * VOCAB_DIM + (size_t)seg * SEG_FLOATS) * 4;

    const uint32_t mbar_a = (uint32_t)__cvta_generic_to_shared(&mbar);
    const uint32_t buf_a  = (uint32_t)__cvta_generic_to_shared(buf);

    // init mbarrier (1 arrival: the expect_tx arrive below)
    if (threadIdx.x == 0) {
        asm volatile("mbarrier.init.shared.b64 [%0], 1;" :: "r"(mbar_a) : "memory");
    }
    __syncthreads();

    // bulk load gmem -> smem, completion via mbarrier transaction bytes
    if (threadIdx.x == 0) {
        asm volatile("mbarrier.arrive.expect_tx.shared.b64 _, [%0], %1;"
                     :: "r"(mbar_a), "r"((uint32_t)SEG_BYTES) : "memory");
        asm volatile(
            "cp.async.bulk.shared::cta.global.mbarrier::complete_tx::bytes "
            "[%0], [%1], %2, [%3];"
            :: "r"(buf_a), "l"((const char*)logits + byte_off),
               "r"((uint32_t)SEG_BYTES), "r"(mbar_a) : "memory");
    }

    // all threads wait for the load (parity 0, single use)
    asm volatile(
        "{\n\t"
        ".reg .pred P;\n\t"
        "WAIT_%=:\n\t"
        "mbarrier.try_wait.parity.shared.b64 P, [%0], 0;\n\t"
        "@!P bra WAIT_%=;\n\t"
        "}" :: "r"(mbar_a) : "memory");

    // penalty fixup directly in smem. Value recomputed from gmem logits so
    // duplicate ids write the same value (no read-modify-write race).
    if (threadIdx.x < PEN_RANGE) {
        const int lo = seg * SEG_FLOATS;
        int id = save_id[row * HIST_DIM + (HIST_DIM - PEN_RANGE) + threadIdx.x];
        int rel = id - lo;
        if (rel >= 0 && rel < SEG_FLOATS) {
            buf[rel] = logits[(size_t)row * VOCAB_DIM + (size_t)id] * penalty[0];
        }
    }
    __syncthreads();
    // order generic smem writes before the async-proxy bulk store reads them
    asm volatile("fence.proxy.async.shared::cta;" ::: "memory");

    // bulk store smem -> gmem
    if (threadIdx.x == 0) {
        asm volatile(
            "cp.async.bulk.global.shared::cta.bulk_group [%0], [%1], %2;"
            :: "l"((char*)out + byte_off), "r"(buf_a),
               "r"((uint32_t)SEG_BYTES) : "memory");
        asm volatile("cp.async.bulk.commit_group;" ::: "memory");
        asm volatile("cp.async.bulk.wait_group 0;" ::: "memory");
    }
}

extern "C" void kernel_launch(void* const* d_in, const int* in_sizes, int n_in,
                              void* d_out, int out_size) {
    const float* logits  = (const float*)d_in[0];
    const int*   save_id = (const int*)d_in[1];
    const float* penalty = (const float*)d_in[2];
    float*       out     = (float*)d_out;

    const int blocks = B_DIM * SEGS_PER_ROW;   // 6400 blocks x 128 threads
    apply_penalty_tma<<<blocks, THREADS>>>(logits, save_id, penalty, out);
}